// round 10
// baseline (speedup 1.0000x reference)
#include <cuda_runtime.h>
#include <cstdint>

#define NIMG 32          // 16 ref + 16 tgt
#define B_   16
#define H_   512
#define W_   512
#define HW_  (H_*W_)

// ---------------- scratch (device globals: allocation-free) ----------------
__device__ unsigned char g_ed [NIMG * HW_];   // 8.4 MB  (bit0 = e, bit1 = d)
__device__ float         g_acc[NIMG * 4];     // zero-init at load; re-zeroed by epilogue

// ---------------- K1: fully fused row-streaming kernel ----------------------
// Block: 256 threads, 2 cols/thread = full 512-px width; strip of 32 output rows.
// Per step i (44 steps): load rgb row rl=y0-6+i -> lum (smem ring, depth 12);
// Sobel E row rE=rl-1 (register shift ring, 2 bytes packed); vertical OR in
// regs; horizontal OR via parity smem row -> ed row rv=rl-3; 7x7 windowed-
// variance vertical update (edr shift ring) + 4-shuffle horizontal + masked
// accumulate.
#define LRING  12
#define LPITCH 528     // cols -4..515 live at idx 0..519 (pads zero), stride 528

__global__ __launch_bounds__(256, 3) void k_fused(const float* __restrict__ ref,
                                                  const float* __restrict__ tgt)
{
    const int img = blockIdx.y;
    const int y0  = blockIdx.x * 32;
    const int t   = threadIdx.x;
    const int w   = t >> 5, l = t & 31;      // 8 warps
    const int c0  = t * 2;

    const float* src = (img < B_) ? (ref + (size_t)img * 3 * HW_)
                                  : (tgt + (size_t)(img - B_) * 3 * HW_);
    unsigned char* edout = g_ed + (size_t)img * HW_;

    __shared__ float    slum[LRING][LPITCH];
    __shared__ unsigned vbuf[2][258];        // idx 1+t; [0] and [257] stay 0
    __shared__ float    RB[2][8][6][3];      // per-warp right halo: {b30, b31, T31}
    __shared__ float    LB[2][8][6][3];      // per-warp left  halo: {T0,  a0,  a1 }

    // zero smem (pads + never-written halo slots must be 0, not garbage/NaN)
    for (int k = t; k < LRING * LPITCH; k += 256) ((float*)slum)[k] = 0.f;
    for (int k = t; k < 2 * 258; k += 256) ((unsigned*)vbuf)[k] = 0u;
    __syncthreads();

    // E shift ring: bit0 = col c0, bit8 = col c0+1 (newest = e4_4, row rE)
    unsigned e4_0 = 0, e4_1 = 0, e4_2 = 0, e4_3 = 0, e4_4 = 0;
    // ed shift ring (2 bytes); OOB rows = 0x0303 (e=d=1 -> both masks 0)
    unsigned edr0 = 0x0303u, edr1 = 0x0303u, edr2 = 0x0303u, edr3 = 0x0303u,
             edr4 = 0x0303u, edr5 = 0x0303u, edr6 = 0x0303u;

    float vs[6][2];
#pragma unroll
    for (int q = 0; q < 6; q++) { vs[q][0] = 0.f; vs[q][1] = 0.f; }

    float accVp = 0.f, accNp = 0.f, accVb = 0.f, accNb = 0.f;

    // prefetch rgb row for step 0
    float2 pr, pg, pb;
    bool pvalid;
    {
        int rl0 = y0 - 6;
        pvalid = (rl0 >= 0 && rl0 < H_);
        if (pvalid) {
            pr = *(const float2*)(src + rl0 * W_ + c0);
            pg = *(const float2*)(src + HW_ + rl0 * W_ + c0);
            pb = *(const float2*)(src + 2 * HW_ + rl0 * W_ + c0);
        }
    }

    int cur = 0;   // lum ring write slot for step i

#pragma unroll 1
    for (int i = 0; i < 44; i++) {
        // ---- lum from prefetched rgb, store to ring ----
        float2 lumv = make_float2(0.f, 0.f);
        if (pvalid) {
            lumv.x = 0.299f * pr.x + 0.587f * pg.x + 0.114f * pb.x;
            lumv.y = 0.299f * pr.y + 0.587f * pg.y + 0.114f * pb.y;
        }
        *(float2*)&slum[cur][4 + c0] = lumv;

        // ---- prefetch next rgb row ----
        {
            int rln = y0 - 5 + i;
            pvalid = (i < 43) && (rln >= 0) && (rln < H_);
            if (pvalid) {
                pr = *(const float2*)(src + rln * W_ + c0);
                pg = *(const float2*)(src + HW_ + rln * W_ + c0);
                pb = *(const float2*)(src + 2 * HW_ + rln * W_ + c0);
            }
        }
        __syncthreads();   // A: lum[rl] visible

        // ---- Sobel E row rE = rl-1 = y0-7+i ----
        unsigned epack = 0;
        {
            const int rE = y0 - 7 + i;
            if (i >= 2 && rE >= 0 && rE < H_) {
                int sa = cur - 2; if (sa < 0) sa += LRING;
                int sb = cur - 1; if (sb < 0) sb += LRING;
                // L[k] = lum col c0-1+k, rows a (rE-1), b (rE), c (rE+1)
                float  La0 = slum[sa][3 + c0];
                float2 La12 = *(const float2*)&slum[sa][4 + c0];
                float  La3 = slum[sa][6 + c0];
                float  Lb0 = slum[sb][3 + c0];
                float2 Lb12 = *(const float2*)&slum[sb][4 + c0];
                float  Lb3 = slum[sb][6 + c0];
                float  Lc0 = slum[cur][3 + c0];
                float2 Lc12 = *(const float2*)&slum[cur][4 + c0];
                float  Lc3 = slum[cur][6 + c0];
                // col c0
                float gx0 = (La12.y - La0) + 2.f * (Lb12.y - Lb0) + (Lc12.y - Lc0);
                float gy0 = (Lc0 - La0) + 2.f * (Lc12.x - La12.x) + (Lc12.y - La12.y);
                // col c0+1
                float gx1 = (La3 - La12.x) + 2.f * (Lb3 - Lb12.x) + (Lc3 - Lc12.x);
                float gy1 = (Lc12.x - La12.x) + 2.f * (Lc12.y - La12.y) + (Lc3 - La3);
                if (gx0 * gx0 + gy0 * gy0 + 1e-12f > 0.01f) epack |= 1u;
                if (gx1 * gx1 + gy1 * gy1 + 1e-12f > 0.01f) epack |= 1u << 8;
            }
        }
        e4_0 = e4_1; e4_1 = e4_2; e4_2 = e4_3; e4_3 = e4_4; e4_4 = epack;

        if (i >= 6) {
            // ---- dilation: vertical OR in regs, horizontal via parity smem ----
            unsigned v = e4_0 | e4_1 | e4_2 | e4_3 | e4_4;
            const int pb2 = i & 1;
            vbuf[pb2][1 + t] = v;

            const int iv = i - 6;
            const int rv = y0 - 3 + iv;

            // ---- variance vertical update needs lum rows rv, rv-7 (own cols) --
            int sn = cur - 3;  if (sn < 0) sn += LRING;
            int so = cur - 10; if (so < 0) so += LRING;
            float2 xv  = *(const float2*)&slum[sn][4 + c0];
            float2 xo2 = *(const float2*)&slum[so][4 + c0];

            __syncthreads();   // B: v row visible
            unsigned vL = vbuf[pb2][t], vR = vbuf[pb2][2 + t];
            unsigned d0 = (vL | (vL >> 8) | v | (v >> 8) | vR) & 1u;
            unsigned d1 = ((vL >> 8) | v | (v >> 8) | vR | (vR >> 8)) & 1u;
            unsigned ed2 = e4_2 | (d0 << 1) | (d1 << 9);   // bytes: {e|d<<1} x2

            if (iv >= 3 && iv <= 34)
                *(unsigned short*)(edout + rv * W_ + c0) = (unsigned short)ed2;
            if (rv < 0 || rv >= H_) ed2 = 0x0303u;         // OOB: both masks 0

#pragma unroll
            for (int c = 0; c < 2; c++) {
                unsigned bn = (ed2  >> (8 * c)) & 3u;
                unsigned bo = (edr0 >> (8 * c)) & 3u;
                float xn  = (&xv.x)[c];
                float xo  = (&xo2.x)[c];
                float mpn = (bn == 2u) ? 1.f : 0.f;
                float mbn = (bn == 0u) ? 1.f : 0.f;
                float mpo = (bo == 2u) ? 1.f : 0.f;
                float mbo = (bo == 0u) ? 1.f : 0.f;
                vs[0][c] += mpn - mpo;
                vs[1][c] += xn * mpn - xo * mpo;
                vs[2][c] += xn * xn * mpn - xo * xo * mpo;
                vs[3][c] += mbn - mbo;
                vs[4][c] += xn * mbn - xo * mbo;
                vs[5][c] += xn * xn * mbn - xo * xo * mbo;
            }
            edr0 = edr1; edr1 = edr2; edr2 = edr3;
            edr3 = edr4; edr4 = edr5; edr5 = edr6; edr6 = ed2;

            // ---- horizontal 7-tap + masked accumulate (output row rv-3) ----
            if (iv >= 6) {
                const int par = iv & 1;
                // publish warp-boundary halos from current vs state
                if (l == 30) {
#pragma unroll
                    for (int q = 0; q < 6; q++) RB[par][w][q][0] = vs[q][1];
                }
                if (l == 31) {
#pragma unroll
                    for (int q = 0; q < 6; q++) {
                        RB[par][w][q][1] = vs[q][1];
                        RB[par][w][q][2] = vs[q][0] + vs[q][1];
                    }
                }
                if (l == 0) {
#pragma unroll
                    for (int q = 0; q < 6; q++) {
                        LB[par][w][q][0] = vs[q][0] + vs[q][1];
                        LB[par][w][q][1] = vs[q][0];
                    }
                }
                if (l == 1) {
#pragma unroll
                    for (int q = 0; q < 6; q++) LB[par][w][q][2] = vs[q][0];
                }
                __syncthreads();   // C: halos visible

                unsigned edc = edr3;           // center row rv-3
#pragma unroll
                for (int g = 0; g < 2; g++) {
                    float S0q[3], S1q[3];
#pragma unroll
                    for (int qq = 0; qq < 3; qq++) {
                        const int q = 3 * g + qq;
                        float a = vs[q][0], b = vs[q][1];
                        float T = a + b;
                        float Tm1 = __shfl_up_sync(0xffffffffu, T, 1);
                        float bm2 = __shfl_up_sync(0xffffffffu, b, 2);
                        float Tp1 = __shfl_down_sync(0xffffffffu, T, 1);
                        float ap2 = __shfl_down_sync(0xffffffffu, a, 2);
                        if (l == 0) {
                            Tm1 = (w > 0) ? RB[par][w - 1][q][2] : 0.f;
                            bm2 = (w > 0) ? RB[par][w - 1][q][0] : 0.f;
                        }
                        if (l == 1)
                            bm2 = (w > 0) ? RB[par][w - 1][q][1] : 0.f;
                        if (l == 31) {
                            Tp1 = (w < 7) ? LB[par][w + 1][q][0] : 0.f;
                            ap2 = (w < 7) ? LB[par][w + 1][q][2] : 0.f;
                        }
                        if (l == 30)
                            ap2 = (w < 7) ? LB[par][w + 1][q][1] : 0.f;
                        float mid = Tm1 + T + Tp1;
                        S0q[qq] = bm2 + mid;       // window at col c0
                        S1q[qq] = mid + ap2;       // window at col c0+1
                    }
                    float aV = 0.f, aN = 0.f;
#pragma unroll
                    for (int c = 0; c < 2; c++) {
                        float Sc = (c == 0) ? S0q[0] : S1q[0];
                        float Sx = (c == 0) ? S0q[1] : S1q[1];
                        float S2 = (c == 0) ? S0q[2] : S1q[2];
                        float cnt = fmaxf(Sc, 1.f);
                        float rcn = __fdividef(1.f, cnt);
                        float mu  = Sx * rcn;
                        float var = fmaxf(S2 * rcn - mu * mu, 0.f);
                        unsigned bc = (edc >> (8 * c)) & 3u;
                        float m = (g == 0) ? ((bc == 2u) ? 1.f : 0.f)
                                           : ((bc == 0u) ? 1.f : 0.f);
                        aV += m * var; aN += m;
                    }
                    if (g == 0) { accVp += aV; accNp += aN; }
                    else        { accVb += aV; accNb += aN; }
                }
            }
        }

        cur++; if (cur == LRING) cur = 0;
    }

    // ---- warp reduce + one atomic per warp per scalar ----
#pragma unroll
    for (int off = 16; off > 0; off >>= 1) {
        accVp += __shfl_down_sync(0xffffffffu, accVp, off);
        accNp += __shfl_down_sync(0xffffffffu, accNp, off);
        accVb += __shfl_down_sync(0xffffffffu, accVb, off);
        accNb += __shfl_down_sync(0xffffffffu, accNb, off);
    }
    if (l == 0) {
        atomicAdd(&g_acc[img * 4 + 0], accVp);
        atomicAdd(&g_acc[img * 4 + 1], accNp);
        atomicAdd(&g_acc[img * 4 + 2], accVb);
        atomicAdd(&g_acc[img * 4 + 3], accNb);
    }
}

// ---------------- K2: flags + output = clip(ringing_tgt - ringing_ref, 0) ---
__global__ void k_output(float* __restrict__ out)
{
    int idx = blockIdx.x * blockDim.x + threadIdx.x;
    const int n4 = B_ * HW_ / 4;
    if (idx >= n4) return;
    int b  = idx / (HW_ / 4);
    int p4 = idx % (HW_ / 4);

    float vpr = g_acc[b * 4 + 0],        npr = g_acc[b * 4 + 1];
    float vbr = g_acc[b * 4 + 2],        nbr = g_acc[b * 4 + 3];
    float vpt = g_acc[(b + B_) * 4 + 0], npt = g_acc[(b + B_) * 4 + 1];
    float vbt = g_acc[(b + B_) * 4 + 2], nbt = g_acc[(b + B_) * 4 + 3];
    float fr = ((vpr / fmaxf(npr, 1.f)) / (vbr / fmaxf(nbr, 1.f) + 1e-12f) > 2.0f) ? 1.f : 0.f;
    float ft = ((vpt / fmaxf(npt, 1.f)) / (vbt / fmaxf(nbt, 1.f) + 1e-12f) > 2.0f) ? 1.f : 0.f;

    const uchar4* edr4 = (const uchar4*)(g_ed + (size_t)b * HW_);
    const uchar4* edt4 = (const uchar4*)(g_ed + (size_t)(b + B_) * HW_);
    uchar4 r4 = edr4[p4], t4 = edt4[p4];

    // byte==2 (d=1,e=0) <=> pixel in M_prox
    float4 o;
    o.x = fmaxf((t4.x == 2 ? ft : 0.f) - (r4.x == 2 ? fr : 0.f), 0.f);
    o.y = fmaxf((t4.y == 2 ? ft : 0.f) - (r4.y == 2 ? fr : 0.f), 0.f);
    o.z = fmaxf((t4.z == 2 ? ft : 0.f) - (r4.z == 2 ? fr : 0.f), 0.f);
    o.w = fmaxf((t4.w == 2 ? ft : 0.f) - (r4.w == 2 ? fr : 0.f), 0.f);
    ((float4*)out)[idx] = o;
}

// ---------------- K3: epilogue — re-zero g_acc for the next (graph) call ----
__global__ void k_zero_acc()
{
    if (threadIdx.x < NIMG * 4) g_acc[threadIdx.x] = 0.f;
}

// ---------------- launch ----------------
extern "C" void kernel_launch(void* const* d_in, const int* in_sizes, int n_in,
                              void* d_out, int out_size)
{
    const float* ref = (const float*)d_in[0];
    const float* tgt = (const float*)d_in[1];

    k_fused<<<dim3(16, NIMG), 256>>>(ref, tgt);

    const int n4 = B_ * HW_ / 4;
    k_output<<<(n4 + 255) / 256, 256>>>((float*)d_out);

    k_zero_acc<<<1, 128>>>();
}

// round 13
// speedup vs baseline: 1.8053x; 1.8053x over previous
#include <cuda_runtime.h>
#include <cstdint>

#define NIMG 32          // 16 ref + 16 tgt
#define B_   16
#define H_   512
#define W_   512
#define HW_  (H_*W_)

// ---------------- scratch (device globals: allocation-free) ----------------
__device__ unsigned char g_ed [NIMG * HW_];   // 8.4 MB  (bit0 = e, bit1 = d)
__device__ float         g_acc[NIMG * 4];     // zero-init at load; re-zeroed by epilogue

// ---------------- K1: fully fused row-streaming kernel ----------------------
// Block: 128 threads, 4 cols/thread = full 512-px width; strip of 16 output
// rows (32 strips/image -> 1024 blocks for occupancy). Per step i (28 steps):
// load rgb row rl=y0-6+i -> lum (smem ring, depth 12); Sobel E row rE=rl-1
// (register shift ring, packed u32); vertical OR in regs; horizontal OR via
// parity smem row -> ed row rv=rl-3; 7x7 windowed-variance vertical update
// (edr shift ring) + shfl horizontal + masked accumulate.
#define STRIP  16
#define NSTEPS (STRIP + 12)    // 28
#define LRING  12
#define LPITCH 528     // cols -4..515 live at idx 0..519 (pads zero), stride 528

__global__ __launch_bounds__(128) void k_fused(const float* __restrict__ ref,
                                               const float* __restrict__ tgt)
{
    const int img = blockIdx.y;
    const int y0  = blockIdx.x * STRIP;
    const int t   = threadIdx.x;
    const int w   = t >> 5, l = t & 31;
    const int c0  = t * 4;

    const float* src = (img < B_) ? (ref + (size_t)img * 3 * HW_)
                                  : (tgt + (size_t)(img - B_) * 3 * HW_);
    unsigned char* edout = g_ed + (size_t)img * HW_;

    __shared__ float    slum[LRING][LPITCH];
    __shared__ unsigned vbuf[2][132];          // idx 1+t; [0] and [129] stay 0
    __shared__ float    sufB[2][4][6][3];
    __shared__ float    preB[2][4][6][3];

    // zero smem (pads + never-written halo slots must be 0, not garbage/NaN)
    for (int k = t; k < LRING * LPITCH; k += 128) ((float*)slum)[k] = 0.f;
    for (int k = t; k < 2 * 132; k += 128) ((unsigned*)vbuf)[k] = 0u;
    __syncthreads();

    // E shift ring (newest = e4_4, row rE; e4_0 = rE-4)
    unsigned e4_0 = 0, e4_1 = 0, e4_2 = 0, e4_3 = 0, e4_4 = 0;
    // ed shift ring for variance window (newest = edr6 = row rv)
    unsigned edr0 = 0x03030303u, edr1 = 0x03030303u, edr2 = 0x03030303u,
             edr3 = 0x03030303u, edr4 = 0x03030303u, edr5 = 0x03030303u,
             edr6 = 0x03030303u;

    float vs[6][4];
#pragma unroll
    for (int q = 0; q < 6; q++)
#pragma unroll
        for (int c = 0; c < 4; c++) vs[q][c] = 0.f;

    float accVp = 0.f, accNp = 0.f, accVb = 0.f, accNb = 0.f;

    // prefetch rgb row for step 0
    float4 pr, pg, pb;
    bool pvalid;
    {
        int rl0 = y0 - 6;
        pvalid = (rl0 >= 0 && rl0 < H_);
        if (pvalid) {
            pr = *(const float4*)(src + rl0 * W_ + c0);
            pg = *(const float4*)(src + HW_ + rl0 * W_ + c0);
            pb = *(const float4*)(src + 2 * HW_ + rl0 * W_ + c0);
        }
    }

    int cur = 0;   // lum ring write slot for step i

#pragma unroll 1
    for (int i = 0; i < NSTEPS; i++) {
        // ---- lum from prefetched rgb, store to ring ----
        float4 lumv = make_float4(0.f, 0.f, 0.f, 0.f);
        if (pvalid) {
            lumv.x = 0.299f * pr.x + 0.587f * pg.x + 0.114f * pb.x;
            lumv.y = 0.299f * pr.y + 0.587f * pg.y + 0.114f * pb.y;
            lumv.z = 0.299f * pr.z + 0.587f * pg.z + 0.114f * pb.z;
            lumv.w = 0.299f * pr.w + 0.587f * pg.w + 0.114f * pb.w;
        }
        *(float4*)&slum[cur][4 + c0] = lumv;

        // ---- prefetch next rgb row ----
        {
            int rln = y0 - 5 + i;
            pvalid = (i < NSTEPS - 1) && (rln >= 0) && (rln < H_);
            if (pvalid) {
                pr = *(const float4*)(src + rln * W_ + c0);
                pg = *(const float4*)(src + HW_ + rln * W_ + c0);
                pb = *(const float4*)(src + 2 * HW_ + rln * W_ + c0);
            }
        }
        __syncthreads();   // A: lum[rl] visible

        // ---- Sobel E row rE = rl-1 = y0-7+i ----
        unsigned epack = 0;
        {
            const int rE = y0 - 7 + i;
            if (i >= 2 && rE >= 0 && rE < H_) {
                int sa = cur - 2; if (sa < 0) sa += LRING;
                int sb = cur - 1; if (sb < 0) sb += LRING;
                float A[6], Bv[6], D[6];
                *(float4*)&A[1]  = *(const float4*)&slum[sa][4 + c0];
                A[0]  = slum[sa][3 + c0];  A[5]  = slum[sa][8 + c0];
                *(float4*)&Bv[1] = *(const float4*)&slum[sb][4 + c0];
                Bv[0] = slum[sb][3 + c0];  Bv[5] = slum[sb][8 + c0];
                *(float4*)&D[1]  = *(const float4*)&slum[cur][4 + c0];
                D[0]  = slum[cur][3 + c0]; D[5]  = slum[cur][8 + c0];
#pragma unroll
                for (int c = 0; c < 4; c++) {
                    float gx = (A[c+2] - A[c]) + 2.f * (Bv[c+2] - Bv[c]) + (D[c+2] - D[c]);
                    float gy = (D[c]   - A[c]) + 2.f * (D[c+1] - A[c+1]) + (D[c+2] - A[c+2]);
                    float g2 = gx * gx + gy * gy + 1e-12f;   // sqrt>0.1 <=> >0.01
                    if (g2 > 0.01f) epack |= 1u << (8 * c);
                }
            }
        }
        e4_0 = e4_1; e4_1 = e4_2; e4_2 = e4_3; e4_3 = e4_4; e4_4 = epack;

        if (i >= 6) {
            // ---- dilation: vertical OR in regs, horizontal via parity smem ----
            unsigned v = e4_0 | e4_1 | e4_2 | e4_3 | e4_4;
            const int pb2 = i & 1;
            vbuf[pb2][1 + t] = v;
            __syncthreads();   // B: v row visible
            unsigned vL = vbuf[pb2][t], vR = vbuf[pb2][2 + t];
            unsigned d4 = v
                        | ((vL >> 16) | (v << 16))
                        | ((vL >> 24) | (v << 8))
                        | ((v >> 8)   | (vR << 24))
                        | ((v >> 16)  | (vR << 16));
            unsigned ed4 = e4_2 | (d4 << 1);   // e of row rd = rE-2 is e4_2

            const int iv = i - 6;
            const int rv = y0 - 3 + iv;        // = rd
            if (iv >= 3 && iv <= STRIP + 2)
                *(unsigned*)(edout + rv * W_ + c0) = ed4;
            if (rv < 0 || rv >= H_) ed4 = 0x03030303u;  // OOB: both masks 0

            // ---- variance vertical update ----
            int sn = cur - 3;  if (sn < 0) sn += LRING;   // lum[rv]
            int so = cur - 10; if (so < 0) so += LRING;   // lum[rv-7]
            float4 xv  = *(const float4*)&slum[sn][4 + c0];
            float4 xo4 = *(const float4*)&slum[so][4 + c0];
#pragma unroll
            for (int c = 0; c < 4; c++) {
                unsigned bn = (ed4  >> (8 * c)) & 3u;
                unsigned bo = (edr0 >> (8 * c)) & 3u;
                float xn  = (&xv.x)[c];
                float xo  = (&xo4.x)[c];
                float mpn = (bn == 2u) ? 1.f : 0.f;
                float mbn = (bn == 0u) ? 1.f : 0.f;
                float mpo = (bo == 2u) ? 1.f : 0.f;
                float mbo = (bo == 0u) ? 1.f : 0.f;
                vs[0][c] += mpn - mpo;
                vs[1][c] += xn * mpn - xo * mpo;
                vs[2][c] += xn * xn * mpn - xo * xo * mpo;
                vs[3][c] += mbn - mbo;
                vs[4][c] += xn * mbn - xo * mbo;
                vs[5][c] += xn * xn * mbn - xo * xo * mbo;
            }
            edr0 = edr1; edr1 = edr2; edr2 = edr3;
            edr3 = edr4; edr4 = edr5; edr5 = edr6; edr6 = ed4;

            // ---- horizontal 7-tap + masked accumulate (output row rv-3) ----
            if (iv >= 6) {
                const int par = iv & 1;
                if (l == 31) {
#pragma unroll
                    for (int q = 0; q < 6; q++) {
                        sufB[par][w][q][0] = vs[q][1] + vs[q][2] + vs[q][3];
                        sufB[par][w][q][1] = vs[q][2] + vs[q][3];
                        sufB[par][w][q][2] = vs[q][3];
                    }
                }
                if (l == 0) {
#pragma unroll
                    for (int q = 0; q < 6; q++) {
                        preB[par][w][q][0] = vs[q][0];
                        preB[par][w][q][1] = vs[q][0] + vs[q][1];
                        preB[par][w][q][2] = vs[q][0] + vs[q][1] + vs[q][2];
                    }
                }
                __syncthreads();   // C: halos visible

                unsigned edc = edr3;           // center row rv-3
#pragma unroll
                for (int g = 0; g < 2; g++) {
                    float Wn[3][4];
#pragma unroll
                    for (int qq = 0; qq < 3; qq++) {
                        const int q = 3 * g + qq;
                        float p0 = vs[q][0];
                        float p1 = p0 + vs[q][1];
                        float p2 = p1 + vs[q][2];
                        float T  = p2 + vs[q][3];
                        float s1 = T - p0, s2 = T - p1, s3 = T - p2;
                        float ls1 = __shfl_up_sync(0xffffffffu, s1, 1);
                        float ls2 = __shfl_up_sync(0xffffffffu, s2, 1);
                        float ls3 = __shfl_up_sync(0xffffffffu, s3, 1);
                        float rp0 = __shfl_down_sync(0xffffffffu, p0, 1);
                        float rp1 = __shfl_down_sync(0xffffffffu, p1, 1);
                        float rp2 = __shfl_down_sync(0xffffffffu, p2, 1);
                        if (l == 0) {
                            ls1 = (w > 0) ? sufB[par][w - 1][q][0] : 0.f;
                            ls2 = (w > 0) ? sufB[par][w - 1][q][1] : 0.f;
                            ls3 = (w > 0) ? sufB[par][w - 1][q][2] : 0.f;
                        }
                        if (l == 31) {
                            rp0 = (w < 3) ? preB[par][w + 1][q][0] : 0.f;
                            rp1 = (w < 3) ? preB[par][w + 1][q][1] : 0.f;
                            rp2 = (w < 3) ? preB[par][w + 1][q][2] : 0.f;
                        }
                        Wn[qq][0] = ls1 + T;
                        Wn[qq][1] = ls2 + T + rp0;
                        Wn[qq][2] = ls3 + T + rp1;
                        Wn[qq][3] = T + rp2;
                    }
                    float aV = 0.f, aN = 0.f;
#pragma unroll
                    for (int c = 0; c < 4; c++) {
                        float cnt = fmaxf(Wn[0][c], 1.f);
                        float rcn = __fdividef(1.f, cnt);
                        float mu  = Wn[1][c] * rcn;
                        float var = fmaxf(Wn[2][c] * rcn - mu * mu, 0.f);
                        unsigned bc = (edc >> (8 * c)) & 3u;
                        float m = (g == 0) ? ((bc == 2u) ? 1.f : 0.f)
                                           : ((bc == 0u) ? 1.f : 0.f);
                        aV += m * var; aN += m;
                    }
                    if (g == 0) { accVp += aV; accNp += aN; }
                    else        { accVb += aV; accNb += aN; }
                }
            }
        }

        cur++; if (cur == LRING) cur = 0;
    }

    // ---- warp reduce + one atomic per warp per scalar ----
#pragma unroll
    for (int off = 16; off > 0; off >>= 1) {
        accVp += __shfl_down_sync(0xffffffffu, accVp, off);
        accNp += __shfl_down_sync(0xffffffffu, accNp, off);
        accVb += __shfl_down_sync(0xffffffffu, accVb, off);
        accNb += __shfl_down_sync(0xffffffffu, accNb, off);
    }
    if (l == 0) {
        atomicAdd(&g_acc[img * 4 + 0], accVp);
        atomicAdd(&g_acc[img * 4 + 1], accNp);
        atomicAdd(&g_acc[img * 4 + 2], accVb);
        atomicAdd(&g_acc[img * 4 + 3], accNb);
    }
}

// ---------------- K2: flags + output = clip(ringing_tgt - ringing_ref, 0) ---
__global__ void k_output(float* __restrict__ out)
{
    int idx = blockIdx.x * blockDim.x + threadIdx.x;
    const int n4 = B_ * HW_ / 4;
    if (idx >= n4) return;
    int b  = idx / (HW_ / 4);
    int p4 = idx % (HW_ / 4);

    float vpr = g_acc[b * 4 + 0],        npr = g_acc[b * 4 + 1];
    float vbr = g_acc[b * 4 + 2],        nbr = g_acc[b * 4 + 3];
    float vpt = g_acc[(b + B_) * 4 + 0], npt = g_acc[(b + B_) * 4 + 1];
    float vbt = g_acc[(b + B_) * 4 + 2], nbt = g_acc[(b + B_) * 4 + 3];
    float fr = ((vpr / fmaxf(npr, 1.f)) / (vbr / fmaxf(nbr, 1.f) + 1e-12f) > 2.0f) ? 1.f : 0.f;
    float ft = ((vpt / fmaxf(npt, 1.f)) / (vbt / fmaxf(nbt, 1.f) + 1e-12f) > 2.0f) ? 1.f : 0.f;

    const uchar4* edr4 = (const uchar4*)(g_ed + (size_t)b * HW_);
    const uchar4* edt4 = (const uchar4*)(g_ed + (size_t)(b + B_) * HW_);
    uchar4 r4 = edr4[p4], t4 = edt4[p4];

    // byte==2 (d=1,e=0) <=> pixel in M_prox
    float4 o;
    o.x = fmaxf((t4.x == 2 ? ft : 0.f) - (r4.x == 2 ? fr : 0.f), 0.f);
    o.y = fmaxf((t4.y == 2 ? ft : 0.f) - (r4.y == 2 ? fr : 0.f), 0.f);
    o.z = fmaxf((t4.z == 2 ? ft : 0.f) - (r4.z == 2 ? fr : 0.f), 0.f);
    o.w = fmaxf((t4.w == 2 ? ft : 0.f) - (r4.w == 2 ? fr : 0.f), 0.f);
    ((float4*)out)[idx] = o;
}

// ---------------- K3: epilogue — re-zero g_acc for the next (graph) call ----
__global__ void k_zero_acc()
{
    if (threadIdx.x < NIMG * 4) g_acc[threadIdx.x] = 0.f;
}

// ---------------- launch ----------------
extern "C" void kernel_launch(void* const* d_in, const int* in_sizes, int n_in,
                              void* d_out, int out_size)
{
    const float* ref = (const float*)d_in[0];
    const float* tgt = (const float*)d_in[1];

    k_fused<<<dim3(H_ / STRIP, NIMG), 128>>>(ref, tgt);

    const int n4 = B_ * HW_ / 4;
    k_output<<<(n4 + 255) / 256, 256>>>((float*)d_out);

    k_zero_acc<<<1, 128>>>();
}